// round 5
// baseline (speedup 1.0000x reference)
#include <cuda_runtime.h>

#define Bb   4
#define Nn   50000
#define Kk   128
#define Ss   256
#define KT   8                  // transforms per scoring block
#define PTS  4                  // points per thread
#define PG   1024               // points per scoring block
#define NG   49                 // ceil(Nn / PG)
#define NBLK (NG * (Kk / KT) * Bb)   // 3136 scoring blocks
#define EPSF 1e-5f

typedef unsigned long long u64;

__device__ float g_transforms[Bb * Kk * 16];   // scalar 4x4 (row-major, for output)
__device__ u64   g_tpacked[Bb * Kk * 12];      // duplicated-pair f32x2 operands
__device__ float g_part[NG * Bb * Kk];         // g-major partial sums
__device__ unsigned int g_cnt = 0;

__device__ __forceinline__ u64 pack2(float lo, float hi) {
    u64 r; asm("mov.b64 %0, {%1,%2};" : "=l"(r) : "f"(lo), "f"(hi)); return r;
}
__device__ __forceinline__ void unpack2(u64 v, float& lo, float& hi) {
    asm("mov.b64 {%0,%1}, %2;" : "=f"(lo), "=f"(hi) : "l"(v));
}
__device__ __forceinline__ u64 fma2(u64 a, u64 b, u64 c) {
    u64 d; asm("fma.rn.f32x2 %0, %1, %2, %3;" : "=l"(d) : "l"(a), "l"(b), "l"(c)); return d;
}
__device__ __forceinline__ u64 add2(u64 a, u64 b) {
    u64 d; asm("add.rn.f32x2 %0, %1, %2;" : "=l"(d) : "l"(a), "l"(b)); return d;
}
__device__ __forceinline__ u64 mul2(u64 a, u64 b) {
    u64 d; asm("mul.rn.f32x2 %0, %1, %2;" : "=l"(d) : "l"(a), "l"(b)); return d;
}
__device__ __forceinline__ float frcp(float x)   { float r; asm("rcp.approx.f32 %0,%1;"   : "=f"(r) : "f"(x)); return r; }
__device__ __forceinline__ float fsqrta(float x) { float r; asm("sqrt.approx.f32 %0,%1;"  : "=f"(r) : "f"(x)); return r; }
__device__ __forceinline__ float frsqrt(float x) { float r; asm("rsqrt.approx.f32 %0,%1;" : "=f"(r) : "f"(x)); return r; }

__device__ __forceinline__ float warp_sum(float v) {
#pragma unroll
    for (int o = 16; o; o >>= 1) v += __shfl_xor_sync(0xffffffffu, v, o);
    return v;
}

// ---------------------------------------------------------------------------
// Kernel 1: warp-per-hypothesis. 64 blocks x 256 thr (8 warps = 8 hypotheses).
// Lane accumulates 8 points of 16 raw moments; butterfly-reduce; lane 0 runs
// Horn quaternion (4x4 Jacobi, approx math) and writes scalar+packed forms.
// ---------------------------------------------------------------------------
__global__ void __launch_bounds__(256)
procrustes_fused_kernel(const float* __restrict__ src,
                        const float* __restrict__ tgt,
                        const float* __restrict__ wgt,
                        const int*   __restrict__ sel) {
    int wid = threadIdx.x >> 5, lane = threadIdx.x & 31;
    int h = blockIdx.x * 8 + wid;     // hypothesis 0..511
    int b = h >> 7, k = h & (Kk - 1);

    float m[16];
#pragma unroll
    for (int q = 0; q < 16; q++) m[q] = 0.f;

#pragma unroll
    for (int j = 0; j < 8; j++) {
        int idx = sel[k * Ss + j * 32 + lane];
        int pb  = (b * Nn + idx) * 3;
        float sx = src[pb + 0], sy = src[pb + 1], sz = src[pb + 2];
        float tx = tgt[pb + 0], ty = tgt[pb + 1], tz = tgt[pb + 2];
        float ww = wgt[b * Nn + idx];
        float wsx = ww * sx, wsy = ww * sy, wsz = ww * sz;
        m[0] += ww;
        m[1] += wsx;      m[2] += wsy;      m[3] += wsz;
        m[4] += ww * tx;  m[5] += ww * ty;  m[6] += ww * tz;
        m[7]  += wsx * tx; m[8]  += wsx * ty; m[9]  += wsx * tz;
        m[10] += wsy * tx; m[11] += wsy * ty; m[12] += wsy * tz;
        m[13] += wsz * tx; m[14] += wsz * ty; m[15] += wsz * tz;
    }
#pragma unroll
    for (int q = 0; q < 16; q++) m[q] = warp_sum(m[q]);

    if (lane == 0) {
        float W    = m[0];
        float invW = 1.0f / (W + EPSF);
        float sig  = W * invW;
        float scx = m[1] * invW, scy = m[2] * invW, scz = m[3] * invW;
        float tcx = m[4] * invW, tcy = m[5] * invW, tcz = m[6] * invW;
        float c2  = 2.0f - sig;
        float Sxx = m[7]  * invW - c2 * scx * tcx;
        float Sxy = m[8]  * invW - c2 * scx * tcy;
        float Sxz = m[9]  * invW - c2 * scx * tcz;
        float Syx = m[10] * invW - c2 * scy * tcx;
        float Syy = m[11] * invW - c2 * scy * tcy;
        float Syz = m[12] * invW - c2 * scy * tcz;
        float Szx = m[13] * invW - c2 * scz * tcx;
        float Szy = m[14] * invW - c2 * scz * tcy;
        float Szz = m[15] * invW - c2 * scz * tcz;

        float A[4][4], V[4][4];
        A[0][0] = Sxx + Syy + Szz; A[0][1] = Syz - Szy; A[0][2] = Szx - Sxz; A[0][3] = Sxy - Syx;
        A[1][1] = Sxx - Syy - Szz; A[1][2] = Sxy + Syx; A[1][3] = Szx + Sxz;
        A[2][2] = -Sxx + Syy - Szz; A[2][3] = Syz + Szy;
        A[3][3] = -Sxx - Syy + Szz;
        A[1][0] = A[0][1]; A[2][0] = A[0][2]; A[3][0] = A[0][3];
        A[2][1] = A[1][2]; A[3][1] = A[1][3]; A[3][2] = A[2][3];
#pragma unroll
        for (int i = 0; i < 4; i++)
#pragma unroll
            for (int j = 0; j < 4; j++) V[i][j] = (i == j) ? 1.f : 0.f;

        for (int sweep = 0; sweep < 6; sweep++) {
#pragma unroll
            for (int p = 0; p < 3; p++) {
#pragma unroll
                for (int q = p + 1; q < 4; q++) {
                    float apq = A[p][q];
                    if (fabsf(apq) > 1e-20f) {
                        float tau = (A[q][q] - A[p][p]) * 0.5f * frcp(apq);
                        float tt  = (tau >= 0.f ? 1.f : -1.f) *
                                    frcp(fabsf(tau) + fsqrta(fmaf(tau, tau, 1.f)));
                        float c = frsqrt(fmaf(tt, tt, 1.f));
                        float sn = tt * c;
#pragma unroll
                        for (int mm = 0; mm < 4; mm++) {
                            float amp = A[mm][p], amq = A[mm][q];
                            A[mm][p] = c * amp - sn * amq;
                            A[mm][q] = sn * amp + c * amq;
                        }
#pragma unroll
                        for (int mm = 0; mm < 4; mm++) {
                            float apm = A[p][mm], aqm = A[q][mm];
                            A[p][mm] = c * apm - sn * aqm;
                            A[q][mm] = sn * apm + c * aqm;
                        }
#pragma unroll
                        for (int mm = 0; mm < 4; mm++) {
                            float vmp = V[mm][p], vmq = V[mm][q];
                            V[mm][p] = c * vmp - sn * vmq;
                            V[mm][q] = sn * vmp + c * vmq;
                        }
                    }
                }
            }
        }
        int jb = 0; float lb = A[0][0];
#pragma unroll
        for (int j = 1; j < 4; j++) { if (A[j][j] > lb) { lb = A[j][j]; jb = j; } }
        float qw = V[0][jb], qx = V[1][jb], qy = V[2][jb], qz = V[3][jb];
        float qn = frsqrt(qw * qw + qx * qx + qy * qy + qz * qz);
        qw *= qn; qx *= qn; qy *= qn; qz *= qn;

        float R00 = 1.f - 2.f * (qy * qy + qz * qz), R01 = 2.f * (qx * qy - qw * qz), R02 = 2.f * (qx * qz + qw * qy);
        float R10 = 2.f * (qx * qy + qw * qz), R11 = 1.f - 2.f * (qx * qx + qz * qz), R12 = 2.f * (qy * qz - qw * qx);
        float R20 = 2.f * (qx * qz - qw * qy), R21 = 2.f * (qy * qz + qw * qx), R22 = 1.f - 2.f * (qx * qx + qy * qy);

        float t0 = tcx - (R00 * scx + R01 * scy + R02 * scz);
        float t1 = tcy - (R10 * scx + R11 * scy + R12 * scz);
        float t2 = tcz - (R20 * scx + R21 * scy + R22 * scz);

        float* T = g_transforms + h * 16;
        T[0] = R00; T[1] = R01; T[2]  = R02; T[3]  = t0;
        T[4] = R10; T[5] = R11; T[6]  = R12; T[7]  = t1;
        T[8] = R20; T[9] = R21; T[10] = R22; T[11] = t2;
        T[12] = 0.f; T[13] = 0.f; T[14] = 0.f; T[15] = 1.f;

        u64* P = g_tpacked + h * 12;
        P[0] = pack2(R00, R00); P[1] = pack2(R01, R01); P[2]  = pack2(R02, R02);
        P[3] = pack2(R10, R10); P[4] = pack2(R11, R11); P[5]  = pack2(R12, R12);
        P[6] = pack2(R20, R20); P[7] = pack2(R21, R21); P[8]  = pack2(R22, R22);
        P[9] = pack2(t0, t0);   P[10] = pack2(t1, t1);  P[11] = pack2(t2, t2);
    }
}

// ---------------------------------------------------------------------------
// Kernel 2: scoring (f32x2, 4 pts/thread, 8 transforms/block, packed-u64
// transform operands from smem) + fused last-block argmin.
// ---------------------------------------------------------------------------
__global__ void __launch_bounds__(256, 3)
score_pick_kernel(const float* __restrict__ src,
                  const float* __restrict__ tgt,
                  const float* __restrict__ wgt,
                  float* __restrict__ out) {
    int g = blockIdx.x, kt = blockIdx.y, b = blockIdx.z;
    int tid = threadIdx.x;
    int lane = tid & 31, wp = tid >> 5;

    // stage this tile's packed transforms in smem
    __shared__ __align__(16) u64 sTp[KT * 12];
    int tb = b * Kk + kt * KT;
    if (tid < KT * 12) sTp[tid] = g_tpacked[tb * 12 + tid];

    // ---- load 4 points ----
    float px[PTS], py[PTS], pz[PTS], wv[PTS];
    float nx[PTS], ny[PTS], nz[PTS];
#pragma unroll
    for (int j = 0; j < PTS; j++) {
        int p = g * PG + j * 256 + tid;
        if (p < Nn) {
            int pb = (b * Nn + p) * 3;
            wv[j] = wgt[b * Nn + p];
            px[j] = src[pb + 0]; py[j] = src[pb + 1]; pz[j] = src[pb + 2];
            nx[j] = -tgt[pb + 0]; ny[j] = -tgt[pb + 1]; nz[j] = -tgt[pb + 2];
        } else {
            wv[j] = 0.f; px[j] = py[j] = pz[j] = 0.f;
            nx[j] = ny[j] = nz[j] = 0.f;
        }
    }
    u64 PX[2], PY[2], PZ[2], NX[2], NY[2], NZ[2];
#pragma unroll
    for (int p = 0; p < 2; p++) {
        PX[p] = pack2(px[2*p], px[2*p+1]);
        PY[p] = pack2(py[2*p], py[2*p+1]);
        PZ[p] = pack2(pz[2*p], pz[2*p+1]);
        NX[p] = pack2(nx[2*p], nx[2*p+1]);
        NY[p] = pack2(ny[2*p], ny[2*p+1]);
        NZ[p] = pack2(nz[2*p], nz[2*p+1]);
    }
    __syncthreads();

    float acc[KT];
#pragma unroll
    for (int kk = 0; kk < KT; kk++) acc[kk] = 0.f;

#pragma unroll
    for (int kk = 0; kk < KT; kk++) {
        const ulonglong2* tp = (const ulonglong2*)&sTp[kk * 12];
        ulonglong2 q0 = tp[0];   // m00 m01
        ulonglong2 q1 = tp[1];   // m02 m10
        ulonglong2 q2 = tp[2];   // m11 m12
        ulonglong2 q3 = tp[3];   // m20 m21
        ulonglong2 q4 = tp[4];   // m22 t0
        ulonglong2 q5 = tp[5];   // t1  t2
        float a = acc[kk];
#pragma unroll
        for (int p = 0; p < 2; p++) {
            u64 dx = fma2(q0.x, PX[p], fma2(q0.y, PY[p], fma2(q1.x, PZ[p], add2(q4.y, NX[p]))));
            u64 dy = fma2(q1.y, PX[p], fma2(q2.x, PY[p], fma2(q2.y, PZ[p], add2(q5.x, NY[p]))));
            u64 dz = fma2(q3.x, PX[p], fma2(q3.y, PY[p], fma2(q4.x, PZ[p], add2(q5.y, NZ[p]))));
            u64 d2 = fma2(dx, dx, fma2(dy, dy, mul2(dz, dz)));
            float d2lo, d2hi;
            unpack2(d2, d2lo, d2hi);
            a = fmaf(wv[2*p],     fsqrta(d2lo), a);
            a = fmaf(wv[2*p + 1], fsqrta(d2hi), a);
        }
        acc[kk] = a;
    }

    // block-reduce 8 accumulators, write g-major partials
    __shared__ float red[KT * 8];
#pragma unroll
    for (int kk = 0; kk < KT; kk++) {
        float v = warp_sum(acc[kk]);
        if (lane == 0) red[kk * 8 + wp] = v;
    }
    __syncthreads();
    if (tid < KT) {
        float s = 0.f;
#pragma unroll
        for (int i = 0; i < 8; i++) s += red[tid * 8 + i];
        g_part[g * (Bb * Kk) + (tb + tid)] = s;
    }

    // ---- last-block argmin + emit ----
    __threadfence();
    __shared__ unsigned s_old;
    if (tid == 0) s_old = atomicAdd(&g_cnt, 1u);
    __syncthreads();
    if (s_old != NBLK - 1) return;
    __threadfence();

    __shared__ float s_err[Bb * Kk];
    {
        float s0 = 0.f, s1 = 0.f;
#pragma unroll
        for (int gg = 0; gg < NG; gg++) {
            s0 += __ldcg(&g_part[gg * (Bb * Kk) + tid]);
            s1 += __ldcg(&g_part[gg * (Bb * Kk) + tid + 256]);
        }
        s_err[tid] = s0;
        s_err[tid + 256] = s1;
    }
    __syncthreads();

    if (wp < Bb) {   // warp wp handles batch wp
        int bb = wp;
        float best = 1e30f; int bi = 0;
#pragma unroll
        for (int r = 0; r < 4; r++) {
            int k = r * 32 + lane;
            float v = s_err[bb * Kk + k];
            if (v < best) { best = v; bi = k; }
        }
#pragma unroll
        for (int o = 16; o; o >>= 1) {
            float oe = __shfl_xor_sync(0xffffffffu, best, o);
            int   oi = __shfl_xor_sync(0xffffffffu, bi, o);
            if (oe < best || (oe == best && oi < bi)) { best = oe; bi = oi; }
        }
        int bk = bb * Kk + __shfl_sync(0xffffffffu, bi, 0);
        if (lane < 16)
            out[bb * 16 + lane] = __ldcg(&g_transforms[bk * 16 + lane]);
    }
    if (tid == 0) g_cnt = 0;   // reset for next graph replay
}

// ---------------------------------------------------------------------------
extern "C" void kernel_launch(void* const* d_in, const int* in_sizes, int n_in,
                              void* d_out, int out_size) {
    const float* src = (const float*)d_in[0];
    const float* tgt = (const float*)d_in[1];
    const float* wgt = (const float*)d_in[2];
    const int*   sel = (const int*)d_in[3];
    float* out = (float*)d_out;

    procrustes_fused_kernel<<<64, 256>>>(src, tgt, wgt, sel);
    dim3 grid2(NG, Kk / KT, Bb);
    score_pick_kernel<<<grid2, 256>>>(src, tgt, wgt, out);
}

// round 7
// speedup vs baseline: 1.0437x; 1.0437x over previous
#include <cuda_runtime.h>

#define Bb   4
#define Nn   50000
#define Kk   128
#define KQ   32                 // transforms per scoring block (quarter of K)
#define NQ   4                  // K quarters
#define Ss   256
#define PTS  8                  // points per thread
#define PG   2048               // points per scoring block
#define NG   25                 // ceil(Nn / PG)
#define NBLK (NG * NQ * Bb)     // 400 scoring blocks
#define EPSF 1e-5f

typedef unsigned long long u64;

__device__ float g_transforms[Bb * Kk * 16];   // scalar 4x4 (row-major, for output)
__device__ u64   g_tpacked[Bb * Kk * 12];      // duplicated-pair f32x2 operands
__device__ float g_part[NG * Bb * Kk];         // [gg][b*K+k] partial sums
__device__ unsigned int g_cnt = 0;

__device__ __forceinline__ u64 pack2(float lo, float hi) {
    u64 r; asm("mov.b64 %0, {%1,%2};" : "=l"(r) : "f"(lo), "f"(hi)); return r;
}
__device__ __forceinline__ void unpack2(u64 v, float& lo, float& hi) {
    asm("mov.b64 {%0,%1}, %2;" : "=f"(lo), "=f"(hi) : "l"(v));
}
__device__ __forceinline__ u64 fma2(u64 a, u64 b, u64 c) {
    u64 d; asm("fma.rn.f32x2 %0, %1, %2, %3;" : "=l"(d) : "l"(a), "l"(b), "l"(c)); return d;
}
__device__ __forceinline__ u64 add2(u64 a, u64 b) {
    u64 d; asm("add.rn.f32x2 %0, %1, %2;" : "=l"(d) : "l"(a), "l"(b)); return d;
}
__device__ __forceinline__ u64 mul2(u64 a, u64 b) {
    u64 d; asm("mul.rn.f32x2 %0, %1, %2;" : "=l"(d) : "l"(a), "l"(b)); return d;
}
__device__ __forceinline__ float frcp(float x)   { float r; asm("rcp.approx.f32 %0,%1;"   : "=f"(r) : "f"(x)); return r; }
__device__ __forceinline__ float fsqrta(float x) { float r; asm("sqrt.approx.f32 %0,%1;"  : "=f"(r) : "f"(x)); return r; }
__device__ __forceinline__ float frsqrt(float x) { float r; asm("rsqrt.approx.f32 %0,%1;" : "=f"(r) : "f"(x)); return r; }

__device__ __forceinline__ float warp_sum(float v) {
#pragma unroll
    for (int o = 16; o; o >>= 1) v += __shfl_xor_sync(0xffffffffu, v, o);
    return v;
}

// ---------------------------------------------------------------------------
// Kernel 1: warp-per-hypothesis. 64 blocks x 256 thr (8 warps = 8 hypotheses).
// Lane accumulates 8 points of 16 raw moments; butterfly-reduce; lane 0 runs
// Horn quaternion (4x4 Jacobi, approx math) and writes scalar+packed forms.
// ---------------------------------------------------------------------------
__global__ void __launch_bounds__(256)
procrustes_fused_kernel(const float* __restrict__ src,
                        const float* __restrict__ tgt,
                        const float* __restrict__ wgt,
                        const int*   __restrict__ sel) {
    int wid = threadIdx.x >> 5, lane = threadIdx.x & 31;
    int h = blockIdx.x * 8 + wid;     // hypothesis 0..511
    int b = h >> 7, k = h & (Kk - 1);

    float m[16];
#pragma unroll
    for (int q = 0; q < 16; q++) m[q] = 0.f;

#pragma unroll
    for (int j = 0; j < 8; j++) {
        int idx = sel[k * Ss + j * 32 + lane];
        int pb  = (b * Nn + idx) * 3;
        float sx = src[pb + 0], sy = src[pb + 1], sz = src[pb + 2];
        float tx = tgt[pb + 0], ty = tgt[pb + 1], tz = tgt[pb + 2];
        float ww = wgt[b * Nn + idx];
        float wsx = ww * sx, wsy = ww * sy, wsz = ww * sz;
        m[0] += ww;
        m[1] += wsx;      m[2] += wsy;      m[3] += wsz;
        m[4] += ww * tx;  m[5] += ww * ty;  m[6] += ww * tz;
        m[7]  += wsx * tx; m[8]  += wsx * ty; m[9]  += wsx * tz;
        m[10] += wsy * tx; m[11] += wsy * ty; m[12] += wsy * tz;
        m[13] += wsz * tx; m[14] += wsz * ty; m[15] += wsz * tz;
    }
#pragma unroll
    for (int q = 0; q < 16; q++) m[q] = warp_sum(m[q]);

    if (lane == 0) {
        float W    = m[0];
        float invW = 1.0f / (W + EPSF);
        float sig  = W * invW;
        float scx = m[1] * invW, scy = m[2] * invW, scz = m[3] * invW;
        float tcx = m[4] * invW, tcy = m[5] * invW, tcz = m[6] * invW;
        float c2  = 2.0f - sig;
        float Sxx = m[7]  * invW - c2 * scx * tcx;
        float Sxy = m[8]  * invW - c2 * scx * tcy;
        float Sxz = m[9]  * invW - c2 * scx * tcz;
        float Syx = m[10] * invW - c2 * scy * tcx;
        float Syy = m[11] * invW - c2 * scy * tcy;
        float Syz = m[12] * invW - c2 * scy * tcz;
        float Szx = m[13] * invW - c2 * scz * tcx;
        float Szy = m[14] * invW - c2 * scz * tcy;
        float Szz = m[15] * invW - c2 * scz * tcz;

        float A[4][4], V[4][4];
        A[0][0] = Sxx + Syy + Szz; A[0][1] = Syz - Szy; A[0][2] = Szx - Sxz; A[0][3] = Sxy - Syx;
        A[1][1] = Sxx - Syy - Szz; A[1][2] = Sxy + Syx; A[1][3] = Szx + Sxz;
        A[2][2] = -Sxx + Syy - Szz; A[2][3] = Syz + Szy;
        A[3][3] = -Sxx - Syy + Szz;
        A[1][0] = A[0][1]; A[2][0] = A[0][2]; A[3][0] = A[0][3];
        A[2][1] = A[1][2]; A[3][1] = A[1][3]; A[3][2] = A[2][3];
#pragma unroll
    for (int i = 0; i < 4; i++)
#pragma unroll
            for (int j = 0; j < 4; j++) V[i][j] = (i == j) ? 1.f : 0.f;

        for (int sweep = 0; sweep < 6; sweep++) {
#pragma unroll
            for (int p = 0; p < 3; p++) {
#pragma unroll
                for (int q = p + 1; q < 4; q++) {
                    float apq = A[p][q];
                    if (fabsf(apq) > 1e-20f) {
                        float tau = (A[q][q] - A[p][p]) * 0.5f * frcp(apq);
                        float tt  = (tau >= 0.f ? 1.f : -1.f) *
                                    frcp(fabsf(tau) + fsqrta(fmaf(tau, tau, 1.f)));
                        float c = frsqrt(fmaf(tt, tt, 1.f));
                        float sn = tt * c;
#pragma unroll
                        for (int mm = 0; mm < 4; mm++) {
                            float amp = A[mm][p], amq = A[mm][q];
                            A[mm][p] = c * amp - sn * amq;
                            A[mm][q] = sn * amp + c * amq;
                        }
#pragma unroll
                        for (int mm = 0; mm < 4; mm++) {
                            float apm = A[p][mm], aqm = A[q][mm];
                            A[p][mm] = c * apm - sn * aqm;
                            A[q][mm] = sn * apm + c * aqm;
                        }
#pragma unroll
                        for (int mm = 0; mm < 4; mm++) {
                            float vmp = V[mm][p], vmq = V[mm][q];
                            V[mm][p] = c * vmp - sn * vmq;
                            V[mm][q] = sn * vmp + c * vmq;
                        }
                    }
                }
            }
        }
        int jb = 0; float lb = A[0][0];
#pragma unroll
        for (int j = 1; j < 4; j++) { if (A[j][j] > lb) { lb = A[j][j]; jb = j; } }
        float qw = V[0][jb], qx = V[1][jb], qy = V[2][jb], qz = V[3][jb];
        float qn = frsqrt(qw * qw + qx * qx + qy * qy + qz * qz);
        qw *= qn; qx *= qn; qy *= qn; qz *= qn;

        float R00 = 1.f - 2.f * (qy * qy + qz * qz), R01 = 2.f * (qx * qy - qw * qz), R02 = 2.f * (qx * qz + qw * qy);
        float R10 = 2.f * (qx * qy + qw * qz), R11 = 1.f - 2.f * (qx * qx + qz * qz), R12 = 2.f * (qy * qz - qw * qx);
        float R20 = 2.f * (qx * qz - qw * qy), R21 = 2.f * (qy * qz + qw * qx), R22 = 1.f - 2.f * (qx * qx + qy * qy);

        float t0 = tcx - (R00 * scx + R01 * scy + R02 * scz);
        float t1 = tcy - (R10 * scx + R11 * scy + R12 * scz);
        float t2 = tcz - (R20 * scx + R21 * scy + R22 * scz);

        float* T = g_transforms + h * 16;
        T[0] = R00; T[1] = R01; T[2]  = R02; T[3]  = t0;
        T[4] = R10; T[5] = R11; T[6]  = R12; T[7]  = t1;
        T[8] = R20; T[9] = R21; T[10] = R22; T[11] = t2;
        T[12] = 0.f; T[13] = 0.f; T[14] = 0.f; T[15] = 1.f;

        u64* P = g_tpacked + h * 12;
        P[0] = pack2(R00, R00); P[1] = pack2(R01, R01); P[2]  = pack2(R02, R02);
        P[3] = pack2(R10, R10); P[4] = pack2(R11, R11); P[5]  = pack2(R12, R12);
        P[6] = pack2(R20, R20); P[7] = pack2(R21, R21); P[8]  = pack2(R22, R22);
        P[9] = pack2(t0, t0);   P[10] = pack2(t1, t1);  P[11] = pack2(t2, t2);
    }
}

// ---------------------------------------------------------------------------
// Kernel 2: scoring. Block = (point-group g, K-quarter q, batch b).
// 8 points loaded ONCE into registers; inner loop over 32 transforms from
// packed smem; acc[32] in regs; fused last-block argmin.
// ---------------------------------------------------------------------------
__global__ void __launch_bounds__(256, 2)
score_pick_kernel(const float* __restrict__ src,
                  const float* __restrict__ tgt,
                  const float* __restrict__ wgt,
                  float* __restrict__ out) {
    int g = blockIdx.x, q = blockIdx.y, b = blockIdx.z;
    int tid = threadIdx.x;
    int lane = tid & 31, wp = tid >> 5;

    // stage this quarter's packed transforms (32 x 12 u64 = 3KB)
    __shared__ __align__(16) u64 sTp[KQ * 12];
    int tb = b * Kk + q * KQ;
    {
        const u64* gp = g_tpacked + tb * 12;
        for (int i = tid; i < KQ * 12; i += 256) sTp[i] = gp[i];
    }

    // ---- load 8 points, pack as 4 f32x2 pairs (targets pre-negated) ----
    u64 PX[4], PY[4], PZ[4], NX[4], NY[4], NZ[4];
    float wv[PTS];
#pragma unroll
    for (int pr = 0; pr < 4; pr++) {
        float v[14];
#pragma unroll
        for (int h = 0; h < 2; h++) {
            int p = g * PG + (pr * 2 + h) * 256 + tid;
            if (p < Nn) {
                int pb = (b * Nn + p) * 3;
                v[h*7+0] = src[pb + 0]; v[h*7+1] = src[pb + 1]; v[h*7+2] = src[pb + 2];
                v[h*7+3] = -tgt[pb + 0]; v[h*7+4] = -tgt[pb + 1]; v[h*7+5] = -tgt[pb + 2];
                v[h*7+6] = wgt[b * Nn + p];
            } else {
                v[h*7+0]=v[h*7+1]=v[h*7+2]=v[h*7+3]=v[h*7+4]=v[h*7+5]=v[h*7+6]=0.f;
            }
        }
        PX[pr] = pack2(v[0], v[7]);
        PY[pr] = pack2(v[1], v[8]);
        PZ[pr] = pack2(v[2], v[9]);
        NX[pr] = pack2(v[3], v[10]);
        NY[pr] = pack2(v[4], v[11]);
        NZ[pr] = pack2(v[5], v[12]);
        wv[pr*2] = v[6]; wv[pr*2+1] = v[13];
    }
    __syncthreads();

    float acc[KQ];
#pragma unroll
    for (int kk = 0; kk < KQ; kk++) acc[kk] = 0.f;

#pragma unroll
    for (int kk = 0; kk < KQ; kk++) {
        const ulonglong2* tp = (const ulonglong2*)&sTp[kk * 12];
        ulonglong2 q0 = tp[0];   // m00 m01
        ulonglong2 q1 = tp[1];   // m02 m10
        ulonglong2 q2 = tp[2];   // m11 m12
        ulonglong2 q3 = tp[3];   // m20 m21
        ulonglong2 q4 = tp[4];   // m22 t0
        ulonglong2 q5 = tp[5];   // t1  t2
        float a = acc[kk];
#pragma unroll
        for (int pr = 0; pr < 4; pr++) {
            u64 dx = fma2(q0.x, PX[pr], fma2(q0.y, PY[pr], fma2(q1.x, PZ[pr], add2(q4.y, NX[pr]))));
            u64 dy = fma2(q1.y, PX[pr], fma2(q2.x, PY[pr], fma2(q2.y, PZ[pr], add2(q5.x, NY[pr]))));
            u64 dz = fma2(q3.x, PX[pr], fma2(q3.y, PY[pr], fma2(q4.x, PZ[pr], add2(q5.y, NZ[pr]))));
            u64 d2 = fma2(dx, dx, fma2(dy, dy, mul2(dz, dz)));
            float d2lo, d2hi;
            unpack2(d2, d2lo, d2hi);
            a = fmaf(wv[2*pr],     fsqrta(d2lo), a);
            a = fmaf(wv[2*pr + 1], fsqrta(d2hi), a);
        }
        acc[kk] = a;
    }

    // block-reduce 32 accumulators, write partials
    __shared__ float red[KQ * 8];
#pragma unroll
    for (int kk = 0; kk < KQ; kk++) {
        float v = warp_sum(acc[kk]);
        if (lane == 0) red[kk * 8 + wp] = v;
    }
    __syncthreads();
    if (tid < KQ) {
        float s = 0.f;
#pragma unroll
        for (int i = 0; i < 8; i++) s += red[tid * 8 + i];
        g_part[g * (Bb * Kk) + (tb + tid)] = s;
    }

    // ---- last-block argmin + emit ----
    __threadfence();
    __shared__ unsigned s_old;
    if (tid == 0) s_old = atomicAdd(&g_cnt, 1u);
    __syncthreads();
    if (s_old != NBLK - 1) return;
    __threadfence();

    __shared__ float s_err[Bb * Kk];
    {
        float s0 = 0.f, s1 = 0.f;
#pragma unroll
        for (int gg = 0; gg < NG; gg++) {
            s0 += __ldcg(&g_part[gg * (Bb * Kk) + tid]);
            s1 += __ldcg(&g_part[gg * (Bb * Kk) + tid + 256]);
        }
        s_err[tid] = s0;
        s_err[tid + 256] = s1;
    }
    __syncthreads();

    if (wp < Bb) {   // warp wp handles batch wp
        int bb = wp;
        float best = 1e30f; int bi = 0;
#pragma unroll
        for (int r = 0; r < 4; r++) {
            int k = r * 32 + lane;
            float v = s_err[bb * Kk + k];
            if (v < best) { best = v; bi = k; }
        }
#pragma unroll
        for (int o = 16; o; o >>= 1) {
            float oe = __shfl_xor_sync(0xffffffffu, best, o);
            int   oi = __shfl_xor_sync(0xffffffffu, bi, o);
            if (oe < best || (oe == best && oi < bi)) { best = oe; bi = oi; }
        }
        int bk = bb * Kk + __shfl_sync(0xffffffffu, bi, 0);
        if (lane < 16)
            out[bb * 16 + lane] = __ldcg(&g_transforms[bk * 16 + lane]);
    }
    if (tid == 0) g_cnt = 0;   // reset for next graph replay
}

// ---------------------------------------------------------------------------
extern "C" void kernel_launch(void* const* d_in, const int* in_sizes, int n_in,
                              void* d_out, int out_size) {
    const float* src = (const float*)d_in[0];
    const float* tgt = (const float*)d_in[1];
    const float* wgt = (const float*)d_in[2];
    const int*   sel = (const int*)d_in[3];
    float* out = (float*)d_out;

    procrustes_fused_kernel<<<64, 256>>>(src, tgt, wgt, sel);
    dim3 grid2(NG, NQ, Bb);
    score_pick_kernel<<<grid2, 256>>>(src, tgt, wgt, out);
}